// round 7
// baseline (speedup 1.0000x reference)
#include <cuda_runtime.h>
#include <cuda_bf16.h>

// Problem constants (fixed by the reference): B=16, H=512, W=512 -> out 2H x 2W
#define BB 16
#define HI 512
#define WI 512
#define HO 1024
#define WO 1024

// Fused: bilinear 2x upsample of mask (half-pixel centers, edge-clamped ==
// JAX renormalized triangle weights), blend fused = xm*xl + ym*yl per channel,
// 3x3 channel-mix (1x1 conv) + bias + relu. Emits (out, x_mask, y_mask).
//
// R5 = R2 mapping + default caching (both proven best) with register-pressure
// work only: 32-bit addressing (all offsets < 2^32) and a 7-blocks/SM
// launch-bounds cap (regs 40 -> <=36) to lift theoretical occupancy 75 -> 87.5%.
__global__ __launch_bounds__(256, 7)
void fused_upsample_mix_kernel(const float* __restrict__ mask,
                               const float* __restrict__ xl,
                               const float* __restrict__ yl,
                               const float* __restrict__ cw,
                               const float* __restrict__ cb,
                               float* __restrict__ out)
{
    const unsigned xq = threadIdx.x;      // 0..255, covers x0 = 4*xq
    const unsigned y  = blockIdx.y;       // 0..HO-1
    const unsigned b  = blockIdx.z;       // 0..B-1

    // Vertical source rows + weights: src_y = y/2 - 0.25
    // y even: rows (y/2 - 1, y/2), weights (0.25, 0.75)
    // y odd : rows (y/2, y/2 + 1), weights (0.75, 0.25)
    unsigned r0, r1; float wy0, wy1;
    const unsigned rh = y >> 1;
    if (y & 1) {
        r0 = rh; r1 = (rh + 1 < HI) ? rh + 1 : HI - 1;
        wy0 = 0.75f; wy1 = 0.25f;
    } else {
        r0 = (rh > 0) ? rh - 1 : 0; r1 = rh;
        wy0 = 0.25f; wy1 = 0.75f;
    }

    // Horizontal: for x in {4q, 4q+1, 4q+2, 4q+3} need input cols
    // t-1, t, t+1, t+2 with t = 2q (clamped at the edges).
    const unsigned t   = xq * 2u;
    const unsigned cm1 = (t > 0u) ? t - 1u : 0u;
    const unsigned c2  = (t + 2u < WI) ? t + 2u : WI - 1u;

    // Upsampled mask values for the 4 output pixels, both channels.
    float m4[2][4];
#pragma unroll
    for (int ch = 0; ch < 2; ch++) {
        const float* p0 = mask + (((b * 2u + ch) * HI + r0) * WI);
        const float* p1 = mask + (((b * 2u + ch) * HI + r1) * WI);
        // Vertical lerp first (matches JAX separable order), then horizontal.
        const float a_m1 = fmaf(wy0, __ldg(p0 + cm1),    wy1 * __ldg(p1 + cm1));
        const float a_0  = fmaf(wy0, __ldg(p0 + t),      wy1 * __ldg(p1 + t));
        const float a_1  = fmaf(wy0, __ldg(p0 + t + 1u), wy1 * __ldg(p1 + t + 1u));
        const float a_2  = fmaf(wy0, __ldg(p0 + c2),     wy1 * __ldg(p1 + c2));
        m4[ch][0] = fmaf(0.25f, a_m1, 0.75f * a_0);   // x = 4q   (even)
        m4[ch][1] = fmaf(0.75f, a_0,  0.25f * a_1);   // x = 4q+1 (odd)
        m4[ch][2] = fmaf(0.25f, a_0,  0.75f * a_1);   // x = 4q+2 (even)
        m4[ch][3] = fmaf(0.75f, a_1,  0.25f * a_2);   // x = 4q+3 (odd)
    }

    // 3x3 channel-mix weights + bias (broadcast, L1-resident).
    const float w00 = __ldg(cw + 0), w01 = __ldg(cw + 1), w02 = __ldg(cw + 2);
    const float w10 = __ldg(cw + 3), w11 = __ldg(cw + 4), w12 = __ldg(cw + 5);
    const float w20 = __ldg(cw + 6), w21 = __ldg(cw + 7), w22 = __ldg(cw + 8);
    const float bs0 = __ldg(cb + 0), bs1 = __ldg(cb + 1), bs2 = __ldg(cb + 2);

    const unsigned planeO  = (unsigned)HO * WO;            // 1,048,576
    const unsigned x0      = xq * 4u;
    const unsigned rowbase = b * 3u * planeO + y * WO + x0;  // < 50.3M, fits u32

    float4 xlv[3], ylv[3];
#pragma unroll
    for (int c = 0; c < 3; c++) {
        xlv[c] = __ldg((const float4*)(xl + rowbase + (unsigned)c * planeO));
        ylv[c] = __ldg((const float4*)(yl + rowbase + (unsigned)c * planeO));
    }

    float4 o0, o1, o2, xmv, ymv;
    float* o0p = (float*)&o0;  float* o1p = (float*)&o1;  float* o2p = (float*)&o2;
    float* xmp = (float*)&xmv; float* ymp = (float*)&ymv;
#pragma unroll
    for (int k = 0; k < 4; k++) {
        const float xm = m4[0][k];
        const float ym = m4[1][k];
        const float f0 = fmaf(xm, ((const float*)&xlv[0])[k], ym * ((const float*)&ylv[0])[k]);
        const float f1 = fmaf(xm, ((const float*)&xlv[1])[k], ym * ((const float*)&ylv[1])[k]);
        const float f2 = fmaf(xm, ((const float*)&xlv[2])[k], ym * ((const float*)&ylv[2])[k]);
        o0p[k] = fmaxf(fmaf(w00, f0, fmaf(w01, f1, fmaf(w02, f2, bs0))), 0.0f);
        o1p[k] = fmaxf(fmaf(w10, f0, fmaf(w11, f1, fmaf(w12, f2, bs1))), 0.0f);
        o2p[k] = fmaxf(fmaf(w20, f0, fmaf(w21, f1, fmaf(w22, f2, bs2))), 0.0f);
        xmp[k] = xm;
        ymp[k] = ym;
    }

    // Output layout: out (B,3,HO,WO), then x_mask (B,1,HO,WO), then y_mask.
    // Default cache policy on stores (evict-first hints measured -3us in R4).
    *(float4*)(out + rowbase)               = o0;
    *(float4*)(out + rowbase + planeO)      = o1;
    *(float4*)(out + rowbase + 2u * planeO) = o2;

    const unsigned maskbase = (unsigned)BB * 3u * planeO
                            + b * planeO + y * WO + x0;   // < 83.9M, fits u32
    *(float4*)(out + maskbase)                        = xmv;
    *(float4*)(out + maskbase + (unsigned)BB * planeO) = ymv;
}

extern "C" void kernel_launch(void* const* d_in, const int* in_sizes, int n_in,
                              void* d_out, int out_size) {
    const float* mask = (const float*)d_in[0];  // (16,2,512,512)
    const float* xl   = (const float*)d_in[1];  // (16,3,1024,1024)
    const float* yl   = (const float*)d_in[2];  // (16,3,1024,1024)
    const float* cw   = (const float*)d_in[3];  // (3,3)
    const float* cb   = (const float*)d_in[4];  // (3,)
    float* out = (float*)d_out;

    dim3 grid(1, HO, BB);   // one block per (row, batch); 256 threads cover WO/4
    dim3 block(256);
    fused_upsample_mix_kernel<<<grid, block>>>(mask, xl, yl, cw, cb, out);
}

// round 8
// speedup vs baseline: 1.2706x; 1.2706x over previous
#include <cuda_runtime.h>
#include <cuda_bf16.h>

// Problem constants (fixed by the reference): B=16, H=512, W=512 -> out 2H x 2W
#define BB 16
#define HI 512
#define WI 512
#define HO 1024
#define WO 1024

// Fused: bilinear 2x upsample of mask (half-pixel centers, edge-clamped ==
// JAX renormalized triangle weights), blend fused = xm*xl + ym*yl per channel,
// 3x3 channel-mix (1x1 conv) + bias + relu. Emits (out, x_mask, y_mask).
//
// R6 = exact R2 configuration (1 output row per block, default cache policy,
// NO occupancy cap — R5's cap caused local-memory spills) with 32-bit
// addressing only (all offsets < 2^32), trimming the 64-bit IMAD chains.
__global__ __launch_bounds__(256)
void fused_upsample_mix_kernel(const float* __restrict__ mask,
                               const float* __restrict__ xl,
                               const float* __restrict__ yl,
                               const float* __restrict__ cw,
                               const float* __restrict__ cb,
                               float* __restrict__ out)
{
    const unsigned xq = threadIdx.x;      // 0..255, covers x0 = 4*xq
    const unsigned y  = blockIdx.y;       // 0..HO-1
    const unsigned b  = blockIdx.z;       // 0..B-1

    // Vertical source rows + weights: src_y = y/2 - 0.25
    // y even: rows (y/2 - 1, y/2), weights (0.25, 0.75)
    // y odd : rows (y/2, y/2 + 1), weights (0.75, 0.25)
    unsigned r0, r1; float wy0, wy1;
    const unsigned rh = y >> 1;
    if (y & 1) {
        r0 = rh; r1 = (rh + 1 < HI) ? rh + 1 : HI - 1;
        wy0 = 0.75f; wy1 = 0.25f;
    } else {
        r0 = (rh > 0) ? rh - 1 : 0; r1 = rh;
        wy0 = 0.25f; wy1 = 0.75f;
    }

    // Horizontal: for x in {4q, 4q+1, 4q+2, 4q+3} need input cols
    // t-1, t, t+1, t+2 with t = 2q (clamped at the edges).
    const unsigned t   = xq * 2u;
    const unsigned cm1 = (t > 0u) ? t - 1u : 0u;
    const unsigned c2  = (t + 2u < WI) ? t + 2u : WI - 1u;

    // Upsampled mask values for the 4 output pixels, both channels.
    float m4[2][4];
#pragma unroll
    for (int ch = 0; ch < 2; ch++) {
        const float* p0 = mask + (((b * 2u + ch) * HI + r0) * WI);
        const float* p1 = mask + (((b * 2u + ch) * HI + r1) * WI);
        // Vertical lerp first (matches JAX separable order), then horizontal.
        const float a_m1 = fmaf(wy0, __ldg(p0 + cm1),    wy1 * __ldg(p1 + cm1));
        const float a_0  = fmaf(wy0, __ldg(p0 + t),      wy1 * __ldg(p1 + t));
        const float a_1  = fmaf(wy0, __ldg(p0 + t + 1u), wy1 * __ldg(p1 + t + 1u));
        const float a_2  = fmaf(wy0, __ldg(p0 + c2),     wy1 * __ldg(p1 + c2));
        m4[ch][0] = fmaf(0.25f, a_m1, 0.75f * a_0);   // x = 4q   (even)
        m4[ch][1] = fmaf(0.75f, a_0,  0.25f * a_1);   // x = 4q+1 (odd)
        m4[ch][2] = fmaf(0.25f, a_0,  0.75f * a_1);   // x = 4q+2 (even)
        m4[ch][3] = fmaf(0.75f, a_1,  0.25f * a_2);   // x = 4q+3 (odd)
    }

    // 3x3 channel-mix weights + bias (broadcast, L1-resident).
    const float w00 = __ldg(cw + 0), w01 = __ldg(cw + 1), w02 = __ldg(cw + 2);
    const float w10 = __ldg(cw + 3), w11 = __ldg(cw + 4), w12 = __ldg(cw + 5);
    const float w20 = __ldg(cw + 6), w21 = __ldg(cw + 7), w22 = __ldg(cw + 8);
    const float bs0 = __ldg(cb + 0), bs1 = __ldg(cb + 1), bs2 = __ldg(cb + 2);

    const unsigned planeO  = (unsigned)HO * WO;              // 1,048,576
    const unsigned x0      = xq * 4u;
    const unsigned rowbase = b * 3u * planeO + y * WO + x0;  // < 50.3M, fits u32

    float4 xlv[3], ylv[3];
#pragma unroll
    for (int c = 0; c < 3; c++) {
        xlv[c] = __ldg((const float4*)(xl + rowbase + (unsigned)c * planeO));
        ylv[c] = __ldg((const float4*)(yl + rowbase + (unsigned)c * planeO));
    }

    float4 o0, o1, o2, xmv, ymv;
    float* o0p = (float*)&o0;  float* o1p = (float*)&o1;  float* o2p = (float*)&o2;
    float* xmp = (float*)&xmv; float* ymp = (float*)&ymv;
#pragma unroll
    for (int k = 0; k < 4; k++) {
        const float xm = m4[0][k];
        const float ym = m4[1][k];
        const float f0 = fmaf(xm, ((const float*)&xlv[0])[k], ym * ((const float*)&ylv[0])[k]);
        const float f1 = fmaf(xm, ((const float*)&xlv[1])[k], ym * ((const float*)&ylv[1])[k]);
        const float f2 = fmaf(xm, ((const float*)&xlv[2])[k], ym * ((const float*)&ylv[2])[k]);
        o0p[k] = fmaxf(fmaf(w00, f0, fmaf(w01, f1, fmaf(w02, f2, bs0))), 0.0f);
        o1p[k] = fmaxf(fmaf(w10, f0, fmaf(w11, f1, fmaf(w12, f2, bs1))), 0.0f);
        o2p[k] = fmaxf(fmaf(w20, f0, fmaf(w21, f1, fmaf(w22, f2, bs2))), 0.0f);
        xmp[k] = xm;
        ymp[k] = ym;
    }

    // Output layout: out (B,3,HO,WO), then x_mask (B,1,HO,WO), then y_mask.
    // Default cache policy (streaming hints measured -3us in R4).
    *(float4*)(out + rowbase)               = o0;
    *(float4*)(out + rowbase + planeO)      = o1;
    *(float4*)(out + rowbase + 2u * planeO) = o2;

    const unsigned maskbase = (unsigned)BB * 3u * planeO
                            + b * planeO + y * WO + x0;   // < 83.9M, fits u32
    *(float4*)(out + maskbase)                         = xmv;
    *(float4*)(out + maskbase + (unsigned)BB * planeO) = ymv;
}

extern "C" void kernel_launch(void* const* d_in, const int* in_sizes, int n_in,
                              void* d_out, int out_size) {
    const float* mask = (const float*)d_in[0];  // (16,2,512,512)
    const float* xl   = (const float*)d_in[1];  // (16,3,1024,1024)
    const float* yl   = (const float*)d_in[2];  // (16,3,1024,1024)
    const float* cw   = (const float*)d_in[3];  // (3,3)
    const float* cb   = (const float*)d_in[4];  // (3,)
    float* out = (float*)d_out;

    dim3 grid(1, HO, BB);   // one block per (row, batch); 256 threads cover WO/4
    dim3 block(256);
    fused_upsample_mix_kernel<<<grid, block>>>(mask, xl, yl, cw, cb, out);
}